// round 5
// baseline (speedup 1.0000x reference)
#include <cuda_runtime.h>
#include <cuda_bf16.h>
#include <math_constants.h>

#define N_NODES   10000
#define N_EDGES   160000
#define E_TOT     170000      // edges + self loops
#define D_MODEL   128
#define NHEAD     8
#define HEAD_DIM  16
#define NUM_LAYERS 7
#define CHUNK     10          // NUM_LABELS + nchunks = 2 + 8
#define NUM_LABELS 2
#define NEG_SLOPE 0.2f

// ---------------- device scratch (no allocation allowed) ----------------
__device__ float g_bufA[N_NODES * D_MODEL];
__device__ float g_bufB[N_NODES * D_MODEL];
__device__ float g_xl[N_NODES * D_MODEL];
__device__ float g_xr[N_NODES * D_MODEL];
__device__ int   g_src[E_TOT];
__device__ int   g_dst[E_TOT];
__device__ int   g_cnt[N_NODES];
__device__ int   g_start[N_NODES + 1];
__device__ int   g_cursor[N_NODES];
__device__ int   g_csr[E_TOT];       // src node ids grouped by dst
__device__ int   g_is64;

// ---------------- packed f32x2 helpers (sm_103 FFMA2 path) ----------------
__device__ __forceinline__ unsigned long long pack2(float x) {
    unsigned long long r;
    asm("mov.b64 %0, {%1, %1};" : "=l"(r) : "f"(x));
    return r;
}
__device__ __forceinline__ void ffma2(unsigned long long& d,
                                      unsigned long long a,
                                      unsigned long long b) {
    asm("fma.rn.f32x2 %0, %1, %2, %0;" : "+l"(d) : "l"(a), "l"(b));
}
__device__ __forceinline__ unsigned long long addf32x2(unsigned long long a,
                                                       unsigned long long b) {
    unsigned long long r;
    asm("add.rn.f32x2 %0, %1, %2;" : "=l"(r) : "l"(a), "l"(b));
    return r;
}

// ---------------- cp.async helpers ----------------
__device__ __forceinline__ unsigned smem_u32(const void* p) {
    unsigned a;
    asm("{ .reg .u64 t; cvta.to.shared.u64 t, %1; cvt.u32.u64 %0, t; }"
        : "=r"(a) : "l"(p));
    return a;
}
__device__ __forceinline__ void cp16(unsigned s, const void* g) {
    asm volatile("cp.async.ca.shared.global [%0], [%1], 16;" :: "r"(s), "l"(g));
}
#define CP_COMMIT() asm volatile("cp.async.commit_group;")

// ------------- dtype detect (int32 vs int64) + zero counters -------------
__global__ void k_detect_zero(const int* __restrict__ e32) {
    int t = blockIdx.x * blockDim.x + threadIdx.x;
    if (t < N_NODES) g_cnt[t] = 0;
    if (blockIdx.x == 0) {
        __shared__ int nz;
        if (threadIdx.x == 0) nz = 0;
        __syncthreads();
        for (int i = threadIdx.x; i < 1024; i += blockDim.x)
            if (e32[2 * i + 1] != 0) nz = 1;
        __syncthreads();
        if (threadIdx.x == 0) g_is64 = (nz == 0) ? 1 : 0;
    }
}

// build src/dst (incl self loops) + histogram of dst
__global__ void k_extract(const int* __restrict__ e32) {
    int t = blockIdx.x * blockDim.x + threadIdx.x;
    if (t >= E_TOT) return;
    int s, d;
    if (t < N_EDGES) {
        if (g_is64) {
            s = e32[2 * t];
            d = e32[2 * (N_EDGES + t)];
        } else {
            s = e32[t];
            d = e32[N_EDGES + t];
        }
    } else {
        s = t - N_EDGES;
        d = s;
    }
    g_src[t] = s;
    g_dst[t] = d;
    atomicAdd(&g_cnt[d], 1);
}

// exclusive scan of g_cnt -> g_start / g_cursor. one block, 1024 threads.
__global__ void __launch_bounds__(1024) k_scan() {
    __shared__ int warpsum[32];
    const int t    = threadIdx.x;
    const int lane = t & 31;
    const int warp = t >> 5;
    const int base = t * 10;

    int local[10];
    int sum = 0;
    #pragma unroll
    for (int i = 0; i < 10; i++) {
        int idx = base + i;
        local[i] = (idx < N_NODES) ? g_cnt[idx] : 0;
        sum += local[i];
    }
    int incl = sum;
    #pragma unroll
    for (int off = 1; off < 32; off <<= 1) {
        int v = __shfl_up_sync(0xffffffffu, incl, off);
        if (lane >= off) incl += v;
    }
    if (lane == 31) warpsum[warp] = incl;
    __syncthreads();
    if (warp == 0) {
        int w = warpsum[lane];
        int wi = w;
        #pragma unroll
        for (int off = 1; off < 32; off <<= 1) {
            int v = __shfl_up_sync(0xffffffffu, wi, off);
            if (lane >= off) wi += v;
        }
        warpsum[lane] = wi - w;   // exclusive
    }
    __syncthreads();
    int run = warpsum[warp] + (incl - sum);
    #pragma unroll
    for (int i = 0; i < 10; i++) {
        int idx = base + i;
        if (idx < N_NODES) {
            g_start[idx]  = run;
            g_cursor[idx] = run;
        }
        run += local[i];
    }
    if (t == 0) g_start[N_NODES] = E_TOT;
}

__global__ void k_scatter() {
    int t = blockIdx.x * blockDim.x + threadIdx.x;
    if (t >= E_TOT) return;
    int d = g_dst[t];
    int pos = atomicAdd(&g_cursor[d], 1);
    g_csr[pos] = g_src[t];
}

// ---------------- fused GEMM: xl = X@Wl + bl ; xr = X@Wr + br -------------
// blockIdx.y: 0 -> (Wl,bl,g_xl) ; 1 -> (Wr,br,g_xr)
// 64x128 tile, BK=16, 256 threads, 4x8 micro-tile, FFMA2,
// cp.async double-buffered pipeline (one tile in flight).
__global__ void __launch_bounds__(256) k_gemm(
    const float* __restrict__ X,
    const float* __restrict__ Wl, const float* __restrict__ bl,
    const float* __restrict__ Wr, const float* __restrict__ br)
{
    const float* W = blockIdx.y ? Wr : Wl;
    const float* b = blockIdx.y ? br : bl;
    float* out = blockIdx.y ? g_xr : g_xl;

    // A: row-major [64][20] (pad 16->20 keeps 16B alignment + kills bank conflicts)
    // B: [16][128]
    __shared__ float As[2][64][20];
    __shared__ float Bs[2][16][128];

    const int tid  = threadIdx.x;
    const int tx   = tid & 15;      // cols tx*8
    const int ty   = tid >> 4;      // rows ty*4
    const int row0 = blockIdx.x * 64;

    // source pointers for this thread's async copies
    const int a_r   = tid >> 2;           // 0..63
    const int a_c4  = (tid & 3) * 4;      // 0,4,8,12
    int a_gr = row0 + a_r;
    if (a_gr >= N_NODES) a_gr = N_NODES - 1;   // clamp (garbage rows not stored)
    const float* a_src = X + a_gr * 128 + a_c4;

    const int b_r0  = tid >> 5;            // 0..7   (f = tid)
    const int b_c40 = (tid & 31) * 4;
    const int b_r1  = (tid + 256) >> 5;    // 8..15  (f = tid+256)
    const int b_c41 = b_c40;

    unsigned a_dst[2], b_dst0[2], b_dst1[2];
    #pragma unroll
    for (int p = 0; p < 2; p++) {
        a_dst[p]  = smem_u32(&As[p][a_r][a_c4]);
        b_dst0[p] = smem_u32(&Bs[p][b_r0][b_c40]);
        b_dst1[p] = smem_u32(&Bs[p][b_r1][b_c41]);
    }

    unsigned long long acc2[4][4];
    #pragma unroll
    for (int i = 0; i < 4; i++)
        #pragma unroll
        for (int j = 0; j < 4; j++) acc2[i][j] = 0ull;

    // prefetch tile 0
    cp16(a_dst[0],  a_src + 0);
    cp16(b_dst0[0], W + b_r0 * 128 + b_c40);
    cp16(b_dst1[0], W + b_r1 * 128 + b_c41);
    CP_COMMIT();

    #pragma unroll
    for (int t = 0; t < 8; t++) {
        const int cur = t & 1;
        if (t < 7) {
            const int nxt = cur ^ 1;
            const int k1 = (t + 1) * 16;
            cp16(a_dst[nxt],  a_src + k1);
            cp16(b_dst0[nxt], W + (k1 + b_r0) * 128 + b_c40);
            cp16(b_dst1[nxt], W + (k1 + b_r1) * 128 + b_c41);
            CP_COMMIT();
            asm volatile("cp.async.wait_group 1;");
        } else {
            asm volatile("cp.async.wait_group 0;");
        }
        __syncthreads();

        #pragma unroll
        for (int k = 0; k < 16; k++) {
            float a0 = As[cur][ty * 4 + 0][k];
            float a1 = As[cur][ty * 4 + 1][k];
            float a2 = As[cur][ty * 4 + 2][k];
            float a3 = As[cur][ty * 4 + 3][k];
            ulonglong2 p01 = *(const ulonglong2*)(&Bs[cur][k][tx * 8 + 0]);
            ulonglong2 p23 = *(const ulonglong2*)(&Bs[cur][k][tx * 8 + 4]);
            unsigned long long A0 = pack2(a0), A1 = pack2(a1);
            unsigned long long A2 = pack2(a2), A3 = pack2(a3);
            ffma2(acc2[0][0], A0, p01.x); ffma2(acc2[0][1], A0, p01.y);
            ffma2(acc2[0][2], A0, p23.x); ffma2(acc2[0][3], A0, p23.y);
            ffma2(acc2[1][0], A1, p01.x); ffma2(acc2[1][1], A1, p01.y);
            ffma2(acc2[1][2], A1, p23.x); ffma2(acc2[1][3], A1, p23.y);
            ffma2(acc2[2][0], A2, p01.x); ffma2(acc2[2][1], A2, p01.y);
            ffma2(acc2[2][2], A2, p23.x); ffma2(acc2[2][3], A2, p23.y);
            ffma2(acc2[3][0], A3, p01.x); ffma2(acc2[3][1], A3, p01.y);
            ffma2(acc2[3][2], A3, p23.x); ffma2(acc2[3][3], A3, p23.y);
        }
        __syncthreads();
    }

    const int c = tx * 8;
    ulonglong2 bp01 = *(const ulonglong2*)(b + c);
    ulonglong2 bp23 = *(const ulonglong2*)(b + c + 4);
    #pragma unroll
    for (int i = 0; i < 4; i++) {
        int gr = row0 + ty * 4 + i;
        if (gr < N_NODES) {
            ulonglong2 o0, o1;
            o0.x = addf32x2(acc2[i][0], bp01.x);
            o0.y = addf32x2(acc2[i][1], bp01.y);
            o1.x = addf32x2(acc2[i][2], bp23.x);
            o1.y = addf32x2(acc2[i][3], bp23.y);
            *(ulonglong2*)(out + gr * 128 + c + 0) = o0;
            *(ulonglong2*)(out + gr * 128 + c + 4) = o1;
        }
    }
}

// ---------------- fused edge kernel: online softmax + aggregate ----------
// TWO warps per node (each runs half the edge list), smem merge.
// lane covers 4 dims (head = lane>>2). Block = 4 warps = 2 nodes.
__global__ void __launch_bounds__(128) k_layer(
    const float* __restrict__ att, const float* __restrict__ bias,
    float* __restrict__ out)
{
    __shared__ float  sm_m[4][32];
    __shared__ float  sm_s[4][32];
    __shared__ float4 sm_a[4][32];

    const int warp = threadIdx.x >> 5;
    const int lane = threadIdx.x & 31;
    const int node = blockIdx.x * 2 + (warp >> 1);
    const int half = warp & 1;
    const int c    = lane * 4;

    const float NINF = __int_as_float(0xFF800000);
    float  m = NINF, s = 0.0f;
    float4 acc = make_float4(0.f, 0.f, 0.f, 0.f);

    if (node < N_NODES) {
        const float4 xr = *(const float4*)(g_xr + node * 128 + c);
        const float4 av = *(const float4*)(att + c);

        const int beg  = g_start[node];
        const int len  = g_start[node + 1] - beg;   // >= 1 (self loop)
        const int lenA = (len + 1) >> 1;
        const int myBeg = half ? (beg + lenA) : beg;
        const int myLen = half ? (len - lenA) : lenA;

        if (myLen > 0) {
            float4 v = *(const float4*)(g_xl + g_csr[myBeg] * 128 + c);
            for (int i = 0; i < myLen; i++) {
                float4 cur = v;
                if (i + 1 < myLen)
                    v = *(const float4*)(g_xl + g_csr[myBeg + i + 1] * 128 + c);
                float zx = cur.x + xr.x; zx = fmaxf(zx, NEG_SLOPE * zx);
                float zy = cur.y + xr.y; zy = fmaxf(zy, NEG_SLOPE * zy);
                float zz = cur.z + xr.z; zz = fmaxf(zz, NEG_SLOPE * zz);
                float zw = cur.w + xr.w; zw = fmaxf(zw, NEG_SLOPE * zw);
                float w = zx * av.x;
                w = fmaf(zy, av.y, w);
                w = fmaf(zz, av.z, w);
                w = fmaf(zw, av.w, w);
                w += __shfl_xor_sync(0xffffffffu, w, 1);
                w += __shfl_xor_sync(0xffffffffu, w, 2);
                float d  = w - m;
                float q  = __expf(-fabsf(d));
                bool  nm = (d > 0.f);
                float p     = nm ? 1.0f : q;
                float scale = nm ? q : 1.0f;
                s = fmaf(s, scale, p);
                acc.x = fmaf(acc.x, scale, p * cur.x);
                acc.y = fmaf(acc.y, scale, p * cur.y);
                acc.z = fmaf(acc.z, scale, p * cur.z);
                acc.w = fmaf(acc.w, scale, p * cur.w);
                m = fmaxf(m, w);
            }
        }
    }

    sm_m[warp][lane] = m;
    sm_s[warp][lane] = s;
    sm_a[warp][lane] = acc;
    __syncthreads();

    if (half == 0 && node < N_NODES) {
        float  mB = sm_m[warp + 1][lane];
        float  sB = sm_s[warp + 1][lane];
        float4 aB = sm_a[warp + 1][lane];
        float mm = fmaxf(m, mB);
        float eA = __expf(m - mm);
        float eB = __expf(mB - mm);     // exp(-inf - finite) = 0 for empty half
        float ss = s * eA + sB * eB;
        float4 aa;
        aa.x = acc.x * eA + aB.x * eB;
        aa.y = acc.y * eA + aB.y * eB;
        aa.z = acc.z * eA + aB.z * eB;
        aa.w = acc.w * eA + aB.w * eB;

        const float inv = 1.0f / (ss + 1e-16f);
        const float4 bi = *(const float4*)(bias + c);
        float4 o;
        o.x = aa.x * inv + bi.x;
        o.y = aa.y * inv + bi.y;
        o.z = aa.z * inv + bi.z;
        o.w = aa.w * inv + bi.w;
        *(float4*)(out + node * 128 + c) = o;
    }
}

// ---------------- final head: out[c,l] = x[c*10+l] . w + b ---------------
__global__ void k_head(const float* __restrict__ xin, const float* __restrict__ w,
                       const float* __restrict__ bh, float* __restrict__ out)
{
    int gt   = blockIdx.x * blockDim.x + threadIdx.x;
    int warp = gt >> 5;
    int lane = gt & 31;
    if (warp >= (N_NODES / CHUNK) * NUM_LABELS) return;
    int c = warp / NUM_LABELS;
    int l = warp % NUM_LABELS;
    const float* row = xin + (c * CHUNK + l) * 128;
    float s = 0.0f;
    #pragma unroll
    for (int i = lane; i < 128; i += 32) s = fmaf(row[i], w[i], s);
    #pragma unroll
    for (int o = 16; o; o >>= 1) s += __shfl_down_sync(0xffffffffu, s, o);
    if (lane == 0) out[warp] = s + bh[0];
}

// ---------------- launch ---------------------------------------------------
extern "C" void kernel_launch(void* const* d_in, const int* in_sizes, int n_in,
                              void* d_out, int out_size)
{
    const float* x    = (const float*)d_in[0];
    const int*   eidx = (const int*)  d_in[1];
    // d_in[2] = nchunks (fixed = 8, chunk = 10; hardcoded)
    const float* Wl   = (const float*)d_in[3];
    const float* bl   = (const float*)d_in[4];
    const float* Wr   = (const float*)d_in[5];
    const float* br   = (const float*)d_in[6];
    const float* att  = (const float*)d_in[7];
    const float* bias = (const float*)d_in[8];
    const float* wh   = (const float*)d_in[9];
    const float* bh   = (const float*)d_in[10];
    float* out = (float*)d_out;

    float *bufA = nullptr, *bufB = nullptr;
    cudaGetSymbolAddress((void**)&bufA, g_bufA);
    cudaGetSymbolAddress((void**)&bufB, g_bufB);

    // CSR build (once per launch)
    k_detect_zero<<<(N_NODES + 255) / 256, 256>>>(eidx);
    k_extract<<<(E_TOT + 255) / 256, 256>>>(eidx);
    k_scan<<<1, 1024>>>();
    k_scatter<<<(E_TOT + 255) / 256, 256>>>();

    const float* cur = x;
    for (int l = 0; l < NUM_LAYERS; l++) {
        float* nxt = (l & 1) ? bufB : bufA;
        dim3 gg((N_NODES + 63) / 64, 2);
        k_gemm<<<gg, 256>>>(cur,
                            Wl + l * D_MODEL * D_MODEL, bl + l * D_MODEL,
                            Wr + l * D_MODEL * D_MODEL, br + l * D_MODEL);
        k_layer<<<(N_NODES + 1) / 2, 128>>>(att + l * NHEAD * HEAD_DIM,
                                            bias + l * D_MODEL, nxt);
        cur = nxt;
    }
    int nwarp = (N_NODES / CHUNK) * NUM_LABELS;  // 2000
    k_head<<<(nwarp * 32 + 255) / 256, 256>>>(cur, wh, bh, out);
}